// round 7
// baseline (speedup 1.0000x reference)
#include <cuda_runtime.h>
#include <cstdint>

// ---------------------------------------------------------------------------
// Network_1760936591970 (sm_103, legacy mma.sync tf32, split-tf32 3-MMA).
// 256 -> 512 -> 512 -> 256 MLP, act(x)=a0*tanh(x)*sin(a1*x+a2)+a3*x+a4,
// fused row softmax (N=256). B=65536, fp32 I/O.
//
// All operands pre-split (Dekker hi/lo tf32) in gmem; mainloop is
// cp.async double-buffer -> swizzled LDS -> HMMA only.
// ---------------------------------------------------------------------------

#define BATCH 65536
#define MT 128
#define NT 256
#define BKT 32
#define STAGE_BYTES 98304   // Ah 16K | Al 16K | Bh 32K | Bl 32K

// pre-split scratch
__device__ uint32_t g_dH[BATCH * 256];     // data hi
__device__ uint32_t g_dL[BATCH * 256];     // data lo
__device__ uint32_t g_h1H[BATCH * 512];
__device__ uint32_t g_h1L[BATCH * 512];
__device__ uint32_t g_h2H[BATCH * 512];
__device__ uint32_t g_h2L[BATCH * 512];
// pre-split, transposed weights [N][K]: L1 @0 (512x256), L2 @131072 (512x512),
// L3 @393216 (256x512)
__device__ uint32_t g_wH[524288];
__device__ uint32_t g_wL[524288];

// ---------------- helpers ----------------
__device__ __forceinline__ uint32_t cvt_tf32(float x) {
    uint32_t r; asm("cvt.rna.tf32.f32 %0, %1;" : "=r"(r) : "f"(x)); return r;
}
__device__ __forceinline__ void split_tf32(float x, uint32_t& h, uint32_t& l) {
    h = cvt_tf32(x);
    l = cvt_tf32(x - __uint_as_float(h));
}
__device__ __forceinline__ uint32_t smem_u32(const void* p) {
    uint32_t a;
    asm("{ .reg .u64 t; cvta.to.shared.u64 t, %1; cvt.u32.u64 %0, t; }" : "=r"(a) : "l"(p));
    return a;
}
__device__ __forceinline__ void mma8(float* c, const uint32_t* a, uint32_t b0, uint32_t b1) {
    asm volatile(
        "mma.sync.aligned.m16n8k8.row.col.f32.tf32.tf32.f32 "
        "{%0,%1,%2,%3},{%4,%5,%6,%7},{%8,%9},{%0,%1,%2,%3};"
        : "+f"(c[0]), "+f"(c[1]), "+f"(c[2]), "+f"(c[3])
        : "r"(a[0]), "r"(a[1]), "r"(a[2]), "r"(a[3]), "r"(b0), "r"(b1));
}
__device__ __forceinline__ void cpa16(uint32_t dst, const void* src) {
    asm volatile("cp.async.cg.shared.global [%0], [%1], 16;" :: "r"(dst), "l"(src));
}
__device__ __forceinline__ float act_f(float x, const float* a) {
    return a[1] * tanhf(x) * sinf(a[2] * x + a[3]) + a[4] * x + a[5];
}
// swizzled byte offset within a 128B k-row: row-major [row][k]
#define ROWOFF(row, kbyte) ((row) * 128 + ((kbyte) ^ (((row) & 7) << 4)))

// ---------------- prep kernels ----------------
__global__ void prep_w(const float* __restrict__ W, uint32_t* __restrict__ th,
                       uint32_t* __restrict__ tl, int K, int N)
{
    int i = blockIdx.x * 256 + threadIdx.x;   // i = n*K + k
    if (i >= N * K) return;
    int n = i / K, k = i - n * K;
    uint32_t h, l;
    split_tf32(W[(size_t)k * N + n], h, l);
    th[i] = h; tl[i] = l;
}
__global__ void prep_a(const float* __restrict__ A, uint32_t* __restrict__ th,
                       uint32_t* __restrict__ tl, int n)
{
    int i = blockIdx.x * 256 + threadIdx.x;
    if (i >= n) return;
    uint32_t h, l;
    split_tf32(A[i], h, l);
    th[i] = h; tl[i] = l;
}

// ---------------- fused GEMM ----------------
// MODE 0: out = split(act(A@Wt + b))   -> outH/outL
// MODE 1: out = softmax(act(A@Wt + b)) -> outF   (requires Nn == 256, grid.x==1)
template <int MODE>
__global__ void __launch_bounds__(256, 1)
gemm_tc(const uint32_t* __restrict__ AH, const uint32_t* __restrict__ AL,
        const uint32_t* __restrict__ BH, const uint32_t* __restrict__ BL,
        const float* __restrict__ bias, const float* __restrict__ actp,
        uint32_t* __restrict__ outH, uint32_t* __restrict__ outL,
        float* __restrict__ outF, int K, int Nn)
{
    extern __shared__ char smem[];
    __shared__ float psm[NT * 6];

    const int tid  = threadIdx.x;
    const int lane = tid & 31;
    const int warp = tid >> 5;
    const int wm   = warp & 1;
    const int wn   = warp >> 1;
    const int g    = lane >> 2;
    const int tg   = lane & 3;
    const int m0   = blockIdx.y * MT;
    const int n0   = blockIdx.x * NT;
    const uint32_t sb = smem_u32(smem);

    for (int c = tid; c < NT; c += 256) {
        psm[c * 6 + 0] = bias[n0 + c];
        #pragma unroll
        for (int j = 0; j < 5; j++) psm[c * 6 + 1 + j] = actp[(n0 + c) * 5 + j];
    }

    float acc[4][8][4];
    #pragma unroll
    for (int i = 0; i < 4; i++)
        #pragma unroll
        for (int j = 0; j < 8; j++)
            #pragma unroll
            for (int c = 0; c < 4; c++) acc[i][j][c] = 0.f;

    const int kIters = K / BKT;

    // per-thread cp.async mapping
    const int am = tid >> 3, aq = tid & 7;        // A: rows tid>>3 (+32 strided)
    const int bn = tid >> 3, bq = tid & 7;        // B: rows tid>>3 (+32 strided)

    auto issue = [&](int it) {
        const uint32_t stb = sb + (it & 1) * STAGE_BYTES;
        const int k0 = it * BKT;
        #pragma unroll
        for (int i = 0; i < 4; i++) {              // A hi+lo: 128 rows
            const int m = am + i * 32;
            const uint32_t off = ROWOFF(m, aq * 16);
            const size_t src = (size_t)(m0 + m) * K + k0 + aq * 4;
            cpa16(stb + off,        AH + src);
            cpa16(stb + 16384 + off, AL + src);
        }
        #pragma unroll
        for (int i = 0; i < 8; i++) {              // B hi+lo: 256 rows
            const int n = bn + i * 32;
            const uint32_t off = ROWOFF(n, bq * 16);
            const size_t src = (size_t)(n0 + n) * K + k0 + bq * 4;
            cpa16(stb + 32768 + off, BH + src);
            cpa16(stb + 65536 + off, BL + src);
        }
        asm volatile("cp.async.commit_group;" ::: "memory");
    };

    issue(0);

    for (int it = 0; it < kIters; it++) {
        if (it + 1 < kIters) {
            issue(it + 1);
            asm volatile("cp.async.wait_group 1;" ::: "memory");
        } else {
            asm volatile("cp.async.wait_group 0;" ::: "memory");
        }
        __syncthreads();

        const char* st = smem + (it & 1) * STAGE_BYTES;
        #pragma unroll
        for (int kk = 0; kk < BKT; kk += 8) {
            uint32_t ah[4][4], al[4][4];
            #pragma unroll
            for (int mi = 0; mi < 4; mi++) {
                #pragma unroll
                for (int r = 0; r < 4; r++) {
                    const int m = wm * 64 + mi * 16 + g + 8 * (r & 1);
                    const int k = kk + tg + 4 * (r >> 1);
                    const uint32_t off = ROWOFF(m, k * 4);
                    ah[mi][r] = *(const uint32_t*)(st + off);
                    al[mi][r] = *(const uint32_t*)(st + 16384 + off);
                }
            }
            #pragma unroll
            for (int ni = 0; ni < 8; ni++) {
                const int n = wn * 64 + ni * 8 + g;
                const uint32_t o0 = ROWOFF(n, (kk + tg) * 4);
                const uint32_t o1 = ROWOFF(n, (kk + tg + 4) * 4);
                const uint32_t bh0 = *(const uint32_t*)(st + 32768 + o0);
                const uint32_t bh1 = *(const uint32_t*)(st + 32768 + o1);
                const uint32_t bl0 = *(const uint32_t*)(st + 65536 + o0);
                const uint32_t bl1 = *(const uint32_t*)(st + 65536 + o1);
                #pragma unroll
                for (int mi = 0; mi < 4; mi++) mma8(acc[mi][ni], ah[mi], bh0, bh1);
                #pragma unroll
                for (int mi = 0; mi < 4; mi++) mma8(acc[mi][ni], al[mi], bh0, bh1);
                #pragma unroll
                for (int mi = 0; mi < 4; mi++) mma8(acc[mi][ni], ah[mi], bl0, bl1);
            }
        }
        __syncthreads();
    }

    // ---- epilogue: bias + activation ----
    #pragma unroll
    for (int mi = 0; mi < 4; mi++)
        #pragma unroll
        for (int ni = 0; ni < 8; ni++) {
            const int cw = wn * 64 + ni * 8 + 2 * tg;
            const float* p0 = &psm[cw * 6];
            const float* p1 = &psm[(cw + 1) * 6];
            acc[mi][ni][0] = act_f(acc[mi][ni][0] + p0[0], p0);
            acc[mi][ni][1] = act_f(acc[mi][ni][1] + p1[0], p1);
            acc[mi][ni][2] = act_f(acc[mi][ni][2] + p0[0], p0);
            acc[mi][ni][3] = act_f(acc[mi][ni][3] + p1[0], p1);
        }

    if (MODE == 0) {
        // split-store hi/lo for the next layer
        #pragma unroll
        for (int mi = 0; mi < 4; mi++)
            #pragma unroll
            for (int ni = 0; ni < 8; ni++) {
                const int col = n0 + wn * 64 + ni * 8 + 2 * tg;
                const int r0 = m0 + wm * 64 + mi * 16 + g;
                uint2 hv, lv;
                split_tf32(acc[mi][ni][0], hv.x, lv.x);
                split_tf32(acc[mi][ni][1], hv.y, lv.y);
                *(uint2*)(outH + (size_t)r0 * Nn + col) = hv;
                *(uint2*)(outL + (size_t)r0 * Nn + col) = lv;
                split_tf32(acc[mi][ni][2], hv.x, lv.x);
                split_tf32(acc[mi][ni][3], hv.y, lv.y);
                *(uint2*)(outH + (size_t)(r0 + 8) * Nn + col) = hv;
                *(uint2*)(outL + (size_t)(r0 + 8) * Nn + col) = lv;
            }
    } else {
        // fused softmax over the full row (Nn == 256 lives in this CTA)
        float* red = (float*)smem;   // [128 rows][4 wn]
        float pmax[4][2], rmax[4][2], psum[4][2], rsum[4][2];

        #pragma unroll
        for (int mi = 0; mi < 4; mi++)
            #pragma unroll
            for (int h = 0; h < 2; h++) {
                float v = -3.4e38f;
                #pragma unroll
                for (int ni = 0; ni < 8; ni++)
                    v = fmaxf(v, fmaxf(acc[mi][ni][2 * h], acc[mi][ni][2 * h + 1]));
                v = fmaxf(v, __shfl_xor_sync(0xFFFFFFFFu, v, 1));
                v = fmaxf(v, __shfl_xor_sync(0xFFFFFFFFu, v, 2));
                pmax[mi][h] = v;
            }
        if (tg == 0)
            #pragma unroll
            for (int mi = 0; mi < 4; mi++)
                #pragma unroll
                for (int h = 0; h < 2; h++)
                    red[(wm * 64 + mi * 16 + g + 8 * h) * 4 + wn] = pmax[mi][h];
        __syncthreads();
        #pragma unroll
        for (int mi = 0; mi < 4; mi++)
            #pragma unroll
            for (int h = 0; h < 2; h++) {
                const int wr = wm * 64 + mi * 16 + g + 8 * h;
                rmax[mi][h] = fmaxf(fmaxf(red[wr * 4 + 0], red[wr * 4 + 1]),
                                    fmaxf(red[wr * 4 + 2], red[wr * 4 + 3]));
            }
        __syncthreads();

        #pragma unroll
        for (int mi = 0; mi < 4; mi++)
            #pragma unroll
            for (int h = 0; h < 2; h++) {
                float s = 0.f;
                #pragma unroll
                for (int ni = 0; ni < 8; ni++) {
                    float e0 = expf(acc[mi][ni][2 * h]     - rmax[mi][h]);
                    float e1 = expf(acc[mi][ni][2 * h + 1] - rmax[mi][h]);
                    acc[mi][ni][2 * h] = e0;
                    acc[mi][ni][2 * h + 1] = e1;
                    s += e0 + e1;
                }
                s += __shfl_xor_sync(0xFFFFFFFFu, s, 1);
                s += __shfl_xor_sync(0xFFFFFFFFu, s, 2);
                psum[mi][h] = s;
            }
        if (tg == 0)
            #pragma unroll
            for (int mi = 0; mi < 4; mi++)
                #pragma unroll
                for (int h = 0; h < 2; h++)
                    red[(wm * 64 + mi * 16 + g + 8 * h) * 4 + wn] = psum[mi][h];
        __syncthreads();
        #pragma unroll
        for (int mi = 0; mi < 4; mi++)
            #pragma unroll
            for (int h = 0; h < 2; h++) {
                const int wr = wm * 64 + mi * 16 + g + 8 * h;
                rsum[mi][h] = 1.0f / (red[wr * 4 + 0] + red[wr * 4 + 1] +
                                      red[wr * 4 + 2] + red[wr * 4 + 3]);
            }

        #pragma unroll
        for (int mi = 0; mi < 4; mi++)
            #pragma unroll
            for (int ni = 0; ni < 8; ni++) {
                const int col = wn * 64 + ni * 8 + 2 * tg;
                const int r0 = m0 + wm * 64 + mi * 16 + g;
                *(float2*)(outF + (size_t)r0 * 256 + col) =
                    make_float2(acc[mi][ni][0] * rsum[mi][0],
                                acc[mi][ni][1] * rsum[mi][0]);
                *(float2*)(outF + (size_t)(r0 + 8) * 256 + col) =
                    make_float2(acc[mi][ni][2] * rsum[mi][1],
                                acc[mi][ni][3] * rsum[mi][1]);
            }
    }
}

// ---------------- launch ----------------
extern "C" void kernel_launch(void* const* d_in, const int* in_sizes, int n_in,
                              void* d_out, int out_size)
{
    (void)in_sizes; (void)n_in; (void)out_size;
    const float* data = (const float*)d_in[0];
    const float* W1   = (const float*)d_in[1];
    const float* b1   = (const float*)d_in[2];
    const float* a1   = (const float*)d_in[3];
    const float* W2   = (const float*)d_in[4];
    const float* b2   = (const float*)d_in[5];
    const float* a2   = (const float*)d_in[6];
    const float* W3   = (const float*)d_in[7];
    const float* b3   = (const float*)d_in[8];
    const float* a3   = (const float*)d_in[9];
    float* out = (float*)d_out;

    void* p;
    cudaGetSymbolAddress(&p, g_dH);  uint32_t* dH  = (uint32_t*)p;
    cudaGetSymbolAddress(&p, g_dL);  uint32_t* dL  = (uint32_t*)p;
    cudaGetSymbolAddress(&p, g_h1H); uint32_t* h1H = (uint32_t*)p;
    cudaGetSymbolAddress(&p, g_h1L); uint32_t* h1L = (uint32_t*)p;
    cudaGetSymbolAddress(&p, g_h2H); uint32_t* h2H = (uint32_t*)p;
    cudaGetSymbolAddress(&p, g_h2L); uint32_t* h2L = (uint32_t*)p;
    cudaGetSymbolAddress(&p, g_wH);  uint32_t* wH  = (uint32_t*)p;
    cudaGetSymbolAddress(&p, g_wL);  uint32_t* wL  = (uint32_t*)p;

    cudaFuncSetAttribute(gemm_tc<0>, cudaFuncAttributeMaxDynamicSharedMemorySize,
                         2 * STAGE_BYTES);
    cudaFuncSetAttribute(gemm_tc<1>, cudaFuncAttributeMaxDynamicSharedMemorySize,
                         2 * STAGE_BYTES);

    prep_w<<<(131072 + 255) / 256, 256>>>(W1, wH,          wL,          256, 512);
    prep_w<<<(262144 + 255) / 256, 256>>>(W2, wH + 131072, wL + 131072, 512, 512);
    prep_w<<<(131072 + 255) / 256, 256>>>(W3, wH + 393216, wL + 393216, 512, 256);
    prep_a<<<(BATCH * 256 + 255) / 256, 256>>>(data, dH, dL, BATCH * 256);

    dim3 blk(256);
    gemm_tc<0><<<dim3(2, BATCH / MT), blk, 2 * STAGE_BYTES>>>(
        dH, dL, wH, wL, b1, a1, h1H, h1L, nullptr, 256, 512);
    gemm_tc<0><<<dim3(2, BATCH / MT), blk, 2 * STAGE_BYTES>>>(
        h1H, h1L, wH + 131072, wL + 131072, b2, a2, h2H, h2L, nullptr, 512, 512);
    gemm_tc<1><<<dim3(1, BATCH / MT), blk, 2 * STAGE_BYTES>>>(
        h2H, h2L, wH + 393216, wL + 393216, b3, a3, nullptr, nullptr, out, 512, 256);
}

// round 9
// speedup vs baseline: 1.4701x; 1.4701x over previous
#include <cuda_runtime.h>
#include <cuda_fp16.h>
#include <cstdint>

// ---------------------------------------------------------------------------
// Network_1760936591970 (sm_103): fp16 2-split (Dekker) x 3-MMA emulated-fp32
// GEMM on mma.sync.m16n8k16.f16 — half the HMMA instruction count of the
// tf32 3-split. 256 -> 512 -> 512 -> 256 MLP, per-node activation, fused
// row softmax (N=256). B=65536, fp32 I/O.
//
// All operands pre-split into packed half2 (hi/lo) arrays in gmem; mainloop
// is cp.async double-buffer -> swizzled LDS -> HMMA only.
// ---------------------------------------------------------------------------

#define BATCH 65536
#define MT 128
#define NT 256
#define BKT 64              // K elements per stage (fp16) = 128 B/row
#define STAGE_BYTES 98304   // Ah 16K | Al 16K | Bh 32K | Bl 32K

// pre-split scratch (uint32 = packed half2 covering k,k+1)
__device__ uint32_t g_dH[BATCH * 128];     // data   [B][256/2]
__device__ uint32_t g_dL[BATCH * 128];
__device__ uint32_t g_h1H[BATCH * 256];    // h1     [B][512/2]
__device__ uint32_t g_h1L[BATCH * 256];
__device__ uint32_t g_h2H[BATCH * 256];    // h2     [B][512/2]
__device__ uint32_t g_h2L[BATCH * 256];
// weights transposed [N][K/2]: L1 @0 (512x128), L2 @65536 (512x256), L3 @196608 (256x256)
__device__ uint32_t g_wH[262144];
__device__ uint32_t g_wL[262144];

// ---------------- helpers ----------------
__device__ __forceinline__ void split_h(float x, uint16_t& h, uint16_t& l) {
    __half hh = __float2half_rn(x);
    __half ll = __float2half_rn(x - __half2float(hh));
    h = __half_as_ushort(hh);
    l = __half_as_ushort(ll);
}
__device__ __forceinline__ uint32_t pack2(uint16_t lo_k, uint16_t hi_k) {
    return (uint32_t)lo_k | ((uint32_t)hi_k << 16);
}
__device__ __forceinline__ uint32_t smem_u32(const void* p) {
    uint32_t a;
    asm("{ .reg .u64 t; cvta.to.shared.u64 t, %1; cvt.u32.u64 %0, t; }" : "=r"(a) : "l"(p));
    return a;
}
__device__ __forceinline__ void mma16(float* c, const uint32_t* a, uint32_t b0, uint32_t b1) {
    asm volatile(
        "mma.sync.aligned.m16n8k16.row.col.f32.f16.f16.f32 "
        "{%0,%1,%2,%3},{%4,%5,%6,%7},{%8,%9},{%0,%1,%2,%3};"
        : "+f"(c[0]), "+f"(c[1]), "+f"(c[2]), "+f"(c[3])
        : "r"(a[0]), "r"(a[1]), "r"(a[2]), "r"(a[3]), "r"(b0), "r"(b1));
}
__device__ __forceinline__ void cpa16(uint32_t dst, const void* src) {
    asm volatile("cp.async.cg.shared.global [%0], [%1], 16;" :: "r"(dst), "l"(src));
}
__device__ __forceinline__ float act_f(float x, const float* a) {
    return a[1] * tanhf(x) * sinf(a[2] * x + a[3]) + a[4] * x + a[5];
}
// swizzled byte offset within a 128B k-row
#define ROWOFF(row, kbyte) ((row) * 128 + ((kbyte) ^ (((row) & 7) << 4)))

// ---------------- prep kernels ----------------
// weights: W[K][N] fp32 -> transposed packed [N][K/2] hi/lo
__global__ void prep_w(const float* __restrict__ W, uint32_t* __restrict__ th,
                       uint32_t* __restrict__ tl, int K, int N)
{
    int i = blockIdx.x * 256 + threadIdx.x;        // i = n*(K/2) + p
    const int Kp = K >> 1;
    if (i >= N * Kp) return;
    int n = i / Kp, p = i - n * Kp;
    uint16_t h0, l0, h1, l1;
    split_h(W[(size_t)(2 * p) * N + n], h0, l0);
    split_h(W[(size_t)(2 * p + 1) * N + n], h1, l1);
    th[i] = pack2(h0, h1);
    tl[i] = pack2(l0, l1);
}
// data: contiguous fp32 -> packed hi/lo (i handles one float4 = 2 pairs)
__global__ void prep_a(const float* __restrict__ A, uint32_t* __restrict__ th,
                       uint32_t* __restrict__ tl, int n4)
{
    int i = blockIdx.x * 256 + threadIdx.x;
    if (i >= n4) return;
    float4 v = *(const float4*)(A + (size_t)i * 4);
    uint16_t h0, l0, h1, l1, h2, l2, h3, l3;
    split_h(v.x, h0, l0); split_h(v.y, h1, l1);
    split_h(v.z, h2, l2); split_h(v.w, h3, l3);
    th[2 * i]     = pack2(h0, h1);  tl[2 * i]     = pack2(l0, l1);
    th[2 * i + 1] = pack2(h2, h3);  tl[2 * i + 1] = pack2(l2, l3);
}

// ---------------- fused GEMM ----------------
// A, B are packed-half2 hi/lo arrays: A [M][K/2], B [N][K/2].
// MODE 0: out = split(act(A@Wt + b)) packed -> outH/outL [M][Nn/2]
// MODE 1: out = softmax(act(A@Wt + b)) -> outF (Nn==256, grid.x==1)
template <int MODE>
__global__ void __launch_bounds__(256, 1)
gemm_tc(const uint32_t* __restrict__ AH, const uint32_t* __restrict__ AL,
        const uint32_t* __restrict__ BH, const uint32_t* __restrict__ BL,
        const float* __restrict__ bias, const float* __restrict__ actp,
        uint32_t* __restrict__ outH, uint32_t* __restrict__ outL,
        float* __restrict__ outF, int K, int Nn)
{
    extern __shared__ char smem[];
    __shared__ float psm[NT * 6];

    const int tid  = threadIdx.x;
    const int lane = tid & 31;
    const int warp = tid >> 5;
    const int wm   = warp & 1;
    const int wn   = warp >> 1;
    const int g    = lane >> 2;
    const int tg   = lane & 3;
    const int m0   = blockIdx.y * MT;
    const int n0   = blockIdx.x * NT;
    const int Kp   = K >> 1;            // gmem row length in uint32 pairs
    const uint32_t sb = smem_u32(smem);

    for (int c = tid; c < NT; c += 256) {
        psm[c * 6 + 0] = bias[n0 + c];
        #pragma unroll
        for (int j = 0; j < 5; j++) psm[c * 6 + 1 + j] = actp[(n0 + c) * 5 + j];
    }

    float acc[4][8][4];
    #pragma unroll
    for (int i = 0; i < 4; i++)
        #pragma unroll
        for (int j = 0; j < 8; j++)
            #pragma unroll
            for (int c = 0; c < 4; c++) acc[i][j][c] = 0.f;

    const int kIters = K / BKT;
    const int am = tid >> 3, aq = tid & 7;   // A: row + 16B chunk
    const int bn = tid >> 3, bq = tid & 7;   // B: row + 16B chunk

    auto issue = [&](int it) {
        const uint32_t stb = sb + (it & 1) * STAGE_BYTES;
        const int p0 = it * 32;              // first k-pair of this stage
        #pragma unroll
        for (int i = 0; i < 4; i++) {        // A hi+lo: 128 rows x 8 chunks
            const int m = am + i * 32;
            const uint32_t off = ROWOFF(m, aq * 16);
            const size_t src = (size_t)(m0 + m) * Kp + p0 + aq * 4;
            cpa16(stb + off,         AH + src);
            cpa16(stb + 16384 + off, AL + src);
        }
        #pragma unroll
        for (int i = 0; i < 8; i++) {        // B hi+lo: 256 rows x 8 chunks
            const int n = bn + i * 32;
            const uint32_t off = ROWOFF(n, bq * 16);
            const size_t src = (size_t)(n0 + n) * Kp + p0 + bq * 4;
            cpa16(stb + 32768 + off, BH + src);
            cpa16(stb + 65536 + off, BL + src);
        }
        asm volatile("cp.async.commit_group;" ::: "memory");
    };

    issue(0);

    for (int it = 0; it < kIters; it++) {
        if (it + 1 < kIters) {
            issue(it + 1);
            asm volatile("cp.async.wait_group 1;" ::: "memory");
        } else {
            asm volatile("cp.async.wait_group 0;" ::: "memory");
        }
        __syncthreads();

        const char* st = smem + (it & 1) * STAGE_BYTES;
        #pragma unroll
        for (int kk = 0; kk < 4; kk++) {     // 4 k16-slices per stage
            const int pA = kk * 8 + tg;      // k-pair indices tg, tg+4
            uint32_t ah[4][4], al[4][4];
            #pragma unroll
            for (int mi = 0; mi < 4; mi++) {
                const int m = wm * 64 + mi * 16 + g;
                const uint32_t o00 = ROWOFF(m,     pA * 4);
                const uint32_t o10 = ROWOFF(m + 8, pA * 4);
                const uint32_t o01 = ROWOFF(m,     (pA + 4) * 4);
                const uint32_t o11 = ROWOFF(m + 8, (pA + 4) * 4);
                ah[mi][0] = *(const uint32_t*)(st + o00);
                ah[mi][1] = *(const uint32_t*)(st + o10);
                ah[mi][2] = *(const uint32_t*)(st + o01);
                ah[mi][3] = *(const uint32_t*)(st + o11);
                al[mi][0] = *(const uint32_t*)(st + 16384 + o00);
                al[mi][1] = *(const uint32_t*)(st + 16384 + o10);
                al[mi][2] = *(const uint32_t*)(st + 16384 + o01);
                al[mi][3] = *(const uint32_t*)(st + 16384 + o11);
            }
            #pragma unroll
            for (int ni = 0; ni < 8; ni++) {
                const int n = wn * 64 + ni * 8 + g;
                const uint32_t o0 = ROWOFF(n, pA * 4);
                const uint32_t o1 = ROWOFF(n, (pA + 4) * 4);
                const uint32_t bh0 = *(const uint32_t*)(st + 32768 + o0);
                const uint32_t bh1 = *(const uint32_t*)(st + 32768 + o1);
                const uint32_t bl0 = *(const uint32_t*)(st + 65536 + o0);
                const uint32_t bl1 = *(const uint32_t*)(st + 65536 + o1);
                #pragma unroll
                for (int mi = 0; mi < 4; mi++) mma16(acc[mi][ni], ah[mi], bh0, bh1);
                #pragma unroll
                for (int mi = 0; mi < 4; mi++) mma16(acc[mi][ni], al[mi], bh0, bh1);
                #pragma unroll
                for (int mi = 0; mi < 4; mi++) mma16(acc[mi][ni], ah[mi], bl0, bl1);
            }
        }
        __syncthreads();
    }

    // ---- epilogue: bias + activation ----
    #pragma unroll
    for (int mi = 0; mi < 4; mi++)
        #pragma unroll
        for (int ni = 0; ni < 8; ni++) {
            const int cw = wn * 64 + ni * 8 + 2 * tg;
            const float* p0 = &psm[cw * 6];
            const float* p1 = &psm[(cw + 1) * 6];
            acc[mi][ni][0] = act_f(acc[mi][ni][0] + p0[0], p0);
            acc[mi][ni][1] = act_f(acc[mi][ni][1] + p1[0], p1);
            acc[mi][ni][2] = act_f(acc[mi][ni][2] + p0[0], p0);
            acc[mi][ni][3] = act_f(acc[mi][ni][3] + p1[0], p1);
        }

    if (MODE == 0) {
        const int Np = Nn >> 1;
        #pragma unroll
        for (int mi = 0; mi < 4; mi++)
            #pragma unroll
            for (int ni = 0; ni < 8; ni++) {
                const int cw = wn * 64 + ni * 8 + 2 * tg;     // even col pair
                const int cp = (n0 + cw) >> 1;                // k-pair index for next layer
                const int r0 = m0 + wm * 64 + mi * 16 + g;
                uint16_t h0, l0, h1, l1;
                split_h(acc[mi][ni][0], h0, l0);
                split_h(acc[mi][ni][1], h1, l1);
                outH[(size_t)r0 * Np + cp] = pack2(h0, h1);
                outL[(size_t)r0 * Np + cp] = pack2(l0, l1);
                split_h(acc[mi][ni][2], h0, l0);
                split_h(acc[mi][ni][3], h1, l1);
                outH[(size_t)(r0 + 8) * Np + cp] = pack2(h0, h1);
                outL[(size_t)(r0 + 8) * Np + cp] = pack2(l0, l1);
            }
    } else {
        // fused softmax over full row (Nn == 256 in this CTA)
        float* red = (float*)smem;   // [128 rows][4 wn]
        float pmax[4][2], rmax[4][2], psum[4][2], rsum[4][2];

        #pragma unroll
        for (int mi = 0; mi < 4; mi++)
            #pragma unroll
            for (int h = 0; h < 2; h++) {
                float v = -3.4e38f;
                #pragma unroll
                for (int ni = 0; ni < 8; ni++)
                    v = fmaxf(v, fmaxf(acc[mi][ni][2 * h], acc[mi][ni][2 * h + 1]));
                v = fmaxf(v, __shfl_xor_sync(0xFFFFFFFFu, v, 1));
                v = fmaxf(v, __shfl_xor_sync(0xFFFFFFFFu, v, 2));
                pmax[mi][h] = v;
            }
        if (tg == 0)
            #pragma unroll
            for (int mi = 0; mi < 4; mi++)
                #pragma unroll
                for (int h = 0; h < 2; h++)
                    red[(wm * 64 + mi * 16 + g + 8 * h) * 4 + wn] = pmax[mi][h];
        __syncthreads();
        #pragma unroll
        for (int mi = 0; mi < 4; mi++)
            #pragma unroll
            for (int h = 0; h < 2; h++) {
                const int wr = wm * 64 + mi * 16 + g + 8 * h;
                rmax[mi][h] = fmaxf(fmaxf(red[wr * 4 + 0], red[wr * 4 + 1]),
                                    fmaxf(red[wr * 4 + 2], red[wr * 4 + 3]));
            }
        __syncthreads();

        #pragma unroll
        for (int mi = 0; mi < 4; mi++)
            #pragma unroll
            for (int h = 0; h < 2; h++) {
                float s = 0.f;
                #pragma unroll
                for (int ni = 0; ni < 8; ni++) {
                    float e0 = expf(acc[mi][ni][2 * h]     - rmax[mi][h]);
                    float e1 = expf(acc[mi][ni][2 * h + 1] - rmax[mi][h]);
                    acc[mi][ni][2 * h]     = e0;
                    acc[mi][ni][2 * h + 1] = e1;
                    s += e0 + e1;
                }
                s += __shfl_xor_sync(0xFFFFFFFFu, s, 1);
                s += __shfl_xor_sync(0xFFFFFFFFu, s, 2);
                psum[mi][h] = s;
            }
        if (tg == 0)
            #pragma unroll
            for (int mi = 0; mi < 4; mi++)
                #pragma unroll
                for (int h = 0; h < 2; h++)
                    red[(wm * 64 + mi * 16 + g + 8 * h) * 4 + wn] = psum[mi][h];
        __syncthreads();
        #pragma unroll
        for (int mi = 0; mi < 4; mi++)
            #pragma unroll
            for (int h = 0; h < 2; h++) {
                const int wr = wm * 64 + mi * 16 + g + 8 * h;
                rsum[mi][h] = 1.0f / (red[wr * 4 + 0] + red[wr * 4 + 1] +
                                      red[wr * 4 + 2] + red[wr * 4 + 3]);
            }

        #pragma unroll
        for (int mi = 0; mi < 4; mi++)
            #pragma unroll
            for (int ni = 0; ni < 8; ni++) {
                const int col = wn * 64 + ni * 8 + 2 * tg;
                const int r0 = m0 + wm * 64 + mi * 16 + g;
                *(float2*)(outF + (size_t)r0 * 256 + col) =
                    make_float2(acc[mi][ni][0] * rsum[mi][0],
                                acc[mi][ni][1] * rsum[mi][0]);
                *(float2*)(outF + (size_t)(r0 + 8) * 256 + col) =
                    make_float2(acc[mi][ni][2] * rsum[mi][1],
                                acc[mi][ni][3] * rsum[mi][1]);
            }
    }
}

// ---------------- launch ----------------
extern "C" void kernel_launch(void* const* d_in, const int* in_sizes, int n_in,
                              void* d_out, int out_size)
{
    (void)in_sizes; (void)n_in; (void)out_size;
    const float* data = (const float*)d_in[0];
    const float* W1   = (const float*)d_in[1];
    const float* b1   = (const float*)d_in[2];
    const float* a1   = (const float*)d_in[3];
    const float* W2   = (const float*)d_in[4];
    const float* b2   = (const float*)d_in[5];
    const float* a2   = (const float*)d_in[6];
    const float* W3   = (const float*)d_in[7];
    const float* b3   = (const float*)d_in[8];
    const float* a3   = (const float*)d_in[9];
    float* out = (float*)d_out;

    void* p;
    cudaGetSymbolAddress(&p, g_dH);  uint32_t* dH  = (uint32_t*)p;
    cudaGetSymbolAddress(&p, g_dL);  uint32_t* dL  = (uint32_t*)p;
    cudaGetSymbolAddress(&p, g_h1H); uint32_t* h1H = (uint32_t*)p;
    cudaGetSymbolAddress(&p, g_h1L); uint32_t* h1L = (uint32_t*)p;
    cudaGetSymbolAddress(&p, g_h2H); uint32_t* h2H = (uint32_t*)p;
    cudaGetSymbolAddress(&p, g_h2L); uint32_t* h2L = (uint32_t*)p;
    cudaGetSymbolAddress(&p, g_wH);  uint32_t* wH  = (uint32_t*)p;
    cudaGetSymbolAddress(&p, g_wL);  uint32_t* wL  = (uint32_t*)p;

    cudaFuncSetAttribute(gemm_tc<0>, cudaFuncAttributeMaxDynamicSharedMemorySize,
                         2 * STAGE_BYTES);
    cudaFuncSetAttribute(gemm_tc<1>, cudaFuncAttributeMaxDynamicSharedMemorySize,
                         2 * STAGE_BYTES);

    // weight prep: [N][K/2] pair-packed, hi/lo
    prep_w<<<(65536  + 255) / 256, 256>>>(W1, wH,          wL,          256, 512);
    prep_w<<<(131072 + 255) / 256, 256>>>(W2, wH + 65536,  wL + 65536,  512, 512);
    prep_w<<<(65536  + 255) / 256, 256>>>(W3, wH + 196608, wL + 196608, 512, 256);
    prep_a<<<(BATCH * 64 + 255) / 256, 256>>>(data, dH, dL, BATCH * 64);

    dim3 blk(256);
    gemm_tc<0><<<dim3(2, BATCH / MT), blk, 2 * STAGE_BYTES>>>(
        dH, dL, wH, wL, b1, a1, h1H, h1L, nullptr, 256, 512);
    gemm_tc<0><<<dim3(2, BATCH / MT), blk, 2 * STAGE_BYTES>>>(
        h1H, h1L, wH + 65536, wL + 65536, b2, a2, h2H, h2L, nullptr, 512, 512);
    gemm_tc<1><<<dim3(1, BATCH / MT), blk, 2 * STAGE_BYTES>>>(
        h2H, h2L, wH + 196608, wL + 196608, b3, a3, nullptr, nullptr, out, 512, 256);
}

// round 10
// speedup vs baseline: 2.1603x; 1.4695x over previous
#include <cuda_runtime.h>
#include <cuda_fp16.h>
#include <cstdint>

// ---------------------------------------------------------------------------
// Network_1760936591970 (sm_103): fp16 2-split (Dekker) x 3-MMA emulated-fp32
// GEMM on mma.sync.m16n8k16.f16. 512-thread CTAs (16 warps, 64x32 warp tiles)
// for latency hiding; fast-tanh epilogue. Fused row softmax in layer 3.
// 256 -> 512 -> 512 -> 256 MLP, B=65536, fp32 I/O.
// ---------------------------------------------------------------------------

#define BATCH 65536
#define MT 128
#define NT 256
#define BKT 64              // K elements per stage (fp16) = 128 B/row
#define STAGE_BYTES 98304   // Ah 16K | Al 16K | Bh 32K | Bl 32K
#define NTHREADS 512

// pre-split scratch (uint32 = packed half2 covering k,k+1)
__device__ uint32_t g_dH[BATCH * 128];     // data   [B][256/2]
__device__ uint32_t g_dL[BATCH * 128];
__device__ uint32_t g_h1H[BATCH * 256];    // h1     [B][512/2]
__device__ uint32_t g_h1L[BATCH * 256];
__device__ uint32_t g_h2H[BATCH * 256];    // h2     [B][512/2]
__device__ uint32_t g_h2L[BATCH * 256];
// weights transposed [N][K/2]: L1 @0, L2 @65536, L3 @196608
__device__ uint32_t g_wH[262144];
__device__ uint32_t g_wL[262144];

// ---------------- helpers ----------------
__device__ __forceinline__ void split_h(float x, uint16_t& h, uint16_t& l) {
    __half hh = __float2half_rn(x);
    __half ll = __float2half_rn(x - __half2float(hh));
    h = __half_as_ushort(hh);
    l = __half_as_ushort(ll);
}
__device__ __forceinline__ uint32_t pack2(uint16_t a, uint16_t b) {
    return (uint32_t)a | ((uint32_t)b << 16);
}
__device__ __forceinline__ uint32_t smem_u32(const void* p) {
    uint32_t a;
    asm("{ .reg .u64 t; cvta.to.shared.u64 t, %1; cvt.u32.u64 %0, t; }" : "=r"(a) : "l"(p));
    return a;
}
__device__ __forceinline__ void mma16(float* c, const uint32_t* a, uint32_t b0, uint32_t b1) {
    asm volatile(
        "mma.sync.aligned.m16n8k16.row.col.f32.f16.f16.f32 "
        "{%0,%1,%2,%3},{%4,%5,%6,%7},{%8,%9},{%0,%1,%2,%3};"
        : "+f"(c[0]), "+f"(c[1]), "+f"(c[2]), "+f"(c[3])
        : "r"(a[0]), "r"(a[1]), "r"(a[2]), "r"(a[3]), "r"(b0), "r"(b1));
}
__device__ __forceinline__ void cpa16(uint32_t dst, const void* src) {
    asm volatile("cp.async.cg.shared.global [%0], [%1], 16;" :: "r"(dst), "l"(src));
}
__device__ __forceinline__ float fast_tanh(float x) {
    float xc = fminf(fmaxf(x, -10.f), 10.f);
    float t = __expf(2.f * xc);
    return __fdividef(t - 1.f, t + 1.f);
}
__device__ __forceinline__ float act_f(float x, const float* a) {
    return a[1] * fast_tanh(x) * sinf(a[2] * x + a[3]) + a[4] * x + a[5];
}
#define ROWOFF(row, kbyte) ((row) * 128 + ((kbyte) ^ (((row) & 7) << 4)))

// ---------------- prep kernels ----------------
__global__ void prep_w(const float* __restrict__ W, uint32_t* __restrict__ th,
                       uint32_t* __restrict__ tl, int K, int N)
{
    int i = blockIdx.x * 256 + threadIdx.x;        // i = n*(K/2) + p
    const int Kp = K >> 1;
    if (i >= N * Kp) return;
    int n = i / Kp, p = i - n * Kp;
    uint16_t h0, l0, h1, l1;
    split_h(W[(size_t)(2 * p) * N + n], h0, l0);
    split_h(W[(size_t)(2 * p + 1) * N + n], h1, l1);
    th[i] = pack2(h0, h1);
    tl[i] = pack2(l0, l1);
}
__global__ void prep_a(const float* __restrict__ A, uint32_t* __restrict__ th,
                       uint32_t* __restrict__ tl, int n4)
{
    int i = blockIdx.x * 256 + threadIdx.x;
    if (i >= n4) return;
    float4 v = *(const float4*)(A + (size_t)i * 4);
    uint16_t h0, l0, h1, l1, h2, l2, h3, l3;
    split_h(v.x, h0, l0); split_h(v.y, h1, l1);
    split_h(v.z, h2, l2); split_h(v.w, h3, l3);
    th[2 * i]     = pack2(h0, h1);  tl[2 * i]     = pack2(l0, l1);
    th[2 * i + 1] = pack2(h2, h3);  tl[2 * i + 1] = pack2(l2, l3);
}

// ---------------- fused GEMM ----------------
// 16 warps: wm = warp&1 (64-row halves), wn = warp>>1 (8 x 32-col blocks).
// MODE 0: out = split(act(A@Wt + b)) packed -> outH/outL [M][Nn/2]
// MODE 1: out = softmax(act(A@Wt + b)) -> outF (Nn==256, grid.x==1)
template <int MODE>
__global__ void __launch_bounds__(NTHREADS, 1)
gemm_tc(const uint32_t* __restrict__ AH, const uint32_t* __restrict__ AL,
        const uint32_t* __restrict__ BH, const uint32_t* __restrict__ BL,
        const float* __restrict__ bias, const float* __restrict__ actp,
        uint32_t* __restrict__ outH, uint32_t* __restrict__ outL,
        float* __restrict__ outF, int K, int Nn)
{
    extern __shared__ char smem[];
    __shared__ float psm[NT * 6];

    const int tid  = threadIdx.x;
    const int lane = tid & 31;
    const int warp = tid >> 5;
    const int wm   = warp & 1;    // 0..1 -> 64-row half
    const int wn   = warp >> 1;   // 0..7 -> 32-col block
    const int g    = lane >> 2;
    const int tg   = lane & 3;
    const int m0   = blockIdx.y * MT;
    const int n0   = blockIdx.x * NT;
    const int Kp   = K >> 1;
    const uint32_t sb = smem_u32(smem);

    for (int c = tid; c < NT; c += NTHREADS) {
        psm[c * 6 + 0] = bias[n0 + c];
        #pragma unroll
        for (int j = 0; j < 5; j++) psm[c * 6 + 1 + j] = actp[(n0 + c) * 5 + j];
    }

    float acc[4][4][4];
    #pragma unroll
    for (int i = 0; i < 4; i++)
        #pragma unroll
        for (int j = 0; j < 4; j++)
            #pragma unroll
            for (int c = 0; c < 4; c++) acc[i][j][c] = 0.f;

    const int kIters = K / BKT;
    // cp.async mapping: 6144 16B-chunks per stage / 512 threads = 12 each
    const int am = tid >> 3, aq = tid & 7;    // A rows 0..63 (+64), chunk 0..7
    const int bn = tid >> 3, bq = tid & 7;    // B rows 0..63 (+64,128,192)

    auto issue = [&](int it) {
        const uint32_t stb = sb + (it & 1) * STAGE_BYTES;
        const int p0 = it * 32;
        #pragma unroll
        for (int i = 0; i < 2; i++) {          // A hi+lo: 128 rows
            const int m = am + i * 64;
            const uint32_t off = ROWOFF(m, aq * 16);
            const size_t src = (size_t)(m0 + m) * Kp + p0 + aq * 4;
            cpa16(stb + off,         AH + src);
            cpa16(stb + 16384 + off, AL + src);
        }
        #pragma unroll
        for (int i = 0; i < 4; i++) {          // B hi+lo: 256 rows
            const int n = bn + i * 64;
            const uint32_t off = ROWOFF(n, bq * 16);
            const size_t src = (size_t)(n0 + n) * Kp + p0 + bq * 4;
            cpa16(stb + 32768 + off, BH + src);
            cpa16(stb + 65536 + off, BL + src);
        }
        asm volatile("cp.async.commit_group;" ::: "memory");
    };

    issue(0);

    for (int it = 0; it < kIters; it++) {
        if (it + 1 < kIters) {
            issue(it + 1);
            asm volatile("cp.async.wait_group 1;" ::: "memory");
        } else {
            asm volatile("cp.async.wait_group 0;" ::: "memory");
        }
        __syncthreads();

        const char* st = smem + (it & 1) * STAGE_BYTES;
        #pragma unroll
        for (int kk = 0; kk < 4; kk++) {       // 4 k16-slices per stage
            const int pA = kk * 8 + tg;
            uint32_t ah[4][4], al[4][4];
            #pragma unroll
            for (int mi = 0; mi < 4; mi++) {
                const int m = wm * 64 + mi * 16 + g;
                const uint32_t o00 = ROWOFF(m,     pA * 4);
                const uint32_t o10 = ROWOFF(m + 8, pA * 4);
                const uint32_t o01 = ROWOFF(m,     (pA + 4) * 4);
                const uint32_t o11 = ROWOFF(m + 8, (pA + 4) * 4);
                ah[mi][0] = *(const uint32_t*)(st + o00);
                ah[mi][1] = *(const uint32_t*)(st + o10);
                ah[mi][2] = *(const uint32_t*)(st + o01);
                ah[mi][3] = *(const uint32_t*)(st + o11);
                al[mi][0] = *(const uint32_t*)(st + 16384 + o00);
                al[mi][1] = *(const uint32_t*)(st + 16384 + o10);
                al[mi][2] = *(const uint32_t*)(st + 16384 + o01);
                al[mi][3] = *(const uint32_t*)(st + 16384 + o11);
            }
            #pragma unroll
            for (int ni = 0; ni < 4; ni++) {
                const int n = wn * 32 + ni * 8 + g;
                const uint32_t o0 = ROWOFF(n, pA * 4);
                const uint32_t o1 = ROWOFF(n, (pA + 4) * 4);
                const uint32_t bh0 = *(const uint32_t*)(st + 32768 + o0);
                const uint32_t bh1 = *(const uint32_t*)(st + 32768 + o1);
                const uint32_t bl0 = *(const uint32_t*)(st + 65536 + o0);
                const uint32_t bl1 = *(const uint32_t*)(st + 65536 + o1);
                #pragma unroll
                for (int mi = 0; mi < 4; mi++) mma16(acc[mi][ni], ah[mi], bh0, bh1);
                #pragma unroll
                for (int mi = 0; mi < 4; mi++) mma16(acc[mi][ni], al[mi], bh0, bh1);
                #pragma unroll
                for (int mi = 0; mi < 4; mi++) mma16(acc[mi][ni], ah[mi], bl0, bl1);
            }
        }
        __syncthreads();
    }

    // ---- epilogue: bias + activation ----
    #pragma unroll
    for (int mi = 0; mi < 4; mi++)
        #pragma unroll
        for (int ni = 0; ni < 4; ni++) {
            const int cw = wn * 32 + ni * 8 + 2 * tg;
            const float* p0 = &psm[cw * 6];
            const float* p1 = &psm[(cw + 1) * 6];
            acc[mi][ni][0] = act_f(acc[mi][ni][0] + p0[0], p0);
            acc[mi][ni][1] = act_f(acc[mi][ni][1] + p1[0], p1);
            acc[mi][ni][2] = act_f(acc[mi][ni][2] + p0[0], p0);
            acc[mi][ni][3] = act_f(acc[mi][ni][3] + p1[0], p1);
        }

    if (MODE == 0) {
        const int Np = Nn >> 1;
        #pragma unroll
        for (int mi = 0; mi < 4; mi++)
            #pragma unroll
            for (int ni = 0; ni < 4; ni++) {
                const int cw = wn * 32 + ni * 8 + 2 * tg;
                const int cp = (n0 + cw) >> 1;
                const int r0 = m0 + wm * 64 + mi * 16 + g;
                uint16_t h0, l0, h1, l1;
                split_h(acc[mi][ni][0], h0, l0);
                split_h(acc[mi][ni][1], h1, l1);
                outH[(size_t)r0 * Np + cp] = pack2(h0, h1);
                outL[(size_t)r0 * Np + cp] = pack2(l0, l1);
                split_h(acc[mi][ni][2], h0, l0);
                split_h(acc[mi][ni][3], h1, l1);
                outH[(size_t)(r0 + 8) * Np + cp] = pack2(h0, h1);
                outL[(size_t)(r0 + 8) * Np + cp] = pack2(l0, l1);
            }
    } else {
        // fused softmax over full row (Nn == 256 in this CTA); 8 wn partials
        float* red = (float*)smem;   // [128 rows][8]
        float pmax[4][2], rmax[4][2], psum[4][2], rsum[4][2];

        #pragma unroll
        for (int mi = 0; mi < 4; mi++)
            #pragma unroll
            for (int h = 0; h < 2; h++) {
                float v = -3.4e38f;
                #pragma unroll
                for (int ni = 0; ni < 4; ni++)
                    v = fmaxf(v, fmaxf(acc[mi][ni][2 * h], acc[mi][ni][2 * h + 1]));
                v = fmaxf(v, __shfl_xor_sync(0xFFFFFFFFu, v, 1));
                v = fmaxf(v, __shfl_xor_sync(0xFFFFFFFFu, v, 2));
                pmax[mi][h] = v;
            }
        if (tg == 0)
            #pragma unroll
            for (int mi = 0; mi < 4; mi++)
                #pragma unroll
                for (int h = 0; h < 2; h++)
                    red[(wm * 64 + mi * 16 + g + 8 * h) * 8 + wn] = pmax[mi][h];
        __syncthreads();
        #pragma unroll
        for (int mi = 0; mi < 4; mi++)
            #pragma unroll
            for (int h = 0; h < 2; h++) {
                const int wr = wm * 64 + mi * 16 + g + 8 * h;
                float v = red[wr * 8 + 0];
                #pragma unroll
                for (int j = 1; j < 8; j++) v = fmaxf(v, red[wr * 8 + j]);
                rmax[mi][h] = v;
            }
        __syncthreads();

        #pragma unroll
        for (int mi = 0; mi < 4; mi++)
            #pragma unroll
            for (int h = 0; h < 2; h++) {
                float s = 0.f;
                #pragma unroll
                for (int ni = 0; ni < 4; ni++) {
                    float e0 = __expf(acc[mi][ni][2 * h]     - rmax[mi][h]);
                    float e1 = __expf(acc[mi][ni][2 * h + 1] - rmax[mi][h]);
                    acc[mi][ni][2 * h]     = e0;
                    acc[mi][ni][2 * h + 1] = e1;
                    s += e0 + e1;
                }
                s += __shfl_xor_sync(0xFFFFFFFFu, s, 1);
                s += __shfl_xor_sync(0xFFFFFFFFu, s, 2);
                psum[mi][h] = s;
            }
        if (tg == 0)
            #pragma unroll
            for (int mi = 0; mi < 4; mi++)
                #pragma unroll
                for (int h = 0; h < 2; h++)
                    red[(wm * 64 + mi * 16 + g + 8 * h) * 8 + wn] = psum[mi][h];
        __syncthreads();
        #pragma unroll
        for (int mi = 0; mi < 4; mi++)
            #pragma unroll
            for (int h = 0; h < 2; h++) {
                const int wr = wm * 64 + mi * 16 + g + 8 * h;
                float s = red[wr * 8 + 0];
                #pragma unroll
                for (int j = 1; j < 8; j++) s += red[wr * 8 + j];
                rsum[mi][h] = 1.0f / s;
            }

        #pragma unroll
        for (int mi = 0; mi < 4; mi++)
            #pragma unroll
            for (int ni = 0; ni < 4; ni++) {
                const int col = wn * 32 + ni * 8 + 2 * tg;
                const int r0 = m0 + wm * 64 + mi * 16 + g;
                *(float2*)(outF + (size_t)r0 * 256 + col) =
                    make_float2(acc[mi][ni][0] * rsum[mi][0],
                                acc[mi][ni][1] * rsum[mi][0]);
                *(float2*)(outF + (size_t)(r0 + 8) * 256 + col) =
                    make_float2(acc[mi][ni][2] * rsum[mi][1],
                                acc[mi][ni][3] * rsum[mi][1]);
            }
    }
}

// ---------------- launch ----------------
extern "C" void kernel_launch(void* const* d_in, const int* in_sizes, int n_in,
                              void* d_out, int out_size)
{
    (void)in_sizes; (void)n_in; (void)out_size;
    const float* data = (const float*)d_in[0];
    const float* W1   = (const float*)d_in[1];
    const float* b1   = (const float*)d_in[2];
    const float* a1   = (const float*)d_in[3];
    const float* W2   = (const float*)d_in[4];
    const float* b2   = (const float*)d_in[5];
    const float* a2   = (const float*)d_in[6];
    const float* W3   = (const float*)d_in[7];
    const float* b3   = (const float*)d_in[8];
    const float* a3   = (const float*)d_in[9];
    float* out = (float*)d_out;

    void* p;
    cudaGetSymbolAddress(&p, g_dH);  uint32_t* dH  = (uint32_t*)p;
    cudaGetSymbolAddress(&p, g_dL);  uint32_t* dL  = (uint32_t*)p;
    cudaGetSymbolAddress(&p, g_h1H); uint32_t* h1H = (uint32_t*)p;
    cudaGetSymbolAddress(&p, g_h1L); uint32_t* h1L = (uint32_t*)p;
    cudaGetSymbolAddress(&p, g_h2H); uint32_t* h2H = (uint32_t*)p;
    cudaGetSymbolAddress(&p, g_h2L); uint32_t* h2L = (uint32_t*)p;
    cudaGetSymbolAddress(&p, g_wH);  uint32_t* wH  = (uint32_t*)p;
    cudaGetSymbolAddress(&p, g_wL);  uint32_t* wL  = (uint32_t*)p;

    cudaFuncSetAttribute(gemm_tc<0>, cudaFuncAttributeMaxDynamicSharedMemorySize,
                         2 * STAGE_BYTES);
    cudaFuncSetAttribute(gemm_tc<1>, cudaFuncAttributeMaxDynamicSharedMemorySize,
                         2 * STAGE_BYTES);

    prep_w<<<(65536  + 255) / 256, 256>>>(W1, wH,          wL,          256, 512);
    prep_w<<<(131072 + 255) / 256, 256>>>(W2, wH + 65536,  wL + 65536,  512, 512);
    prep_w<<<(65536  + 255) / 256, 256>>>(W3, wH + 196608, wL + 196608, 512, 256);
    prep_a<<<(BATCH * 64 + 255) / 256, 256>>>(data, dH, dL, BATCH * 64);

    dim3 blk(NTHREADS);
    gemm_tc<0><<<dim3(2, BATCH / MT), blk, 2 * STAGE_BYTES>>>(
        dH, dL, wH, wL, b1, a1, h1H, h1L, nullptr, 256, 512);
    gemm_tc<0><<<dim3(2, BATCH / MT), blk, 2 * STAGE_BYTES>>>(
        h1H, h1L, wH + 65536, wL + 65536, b2, a2, h2H, h2L, nullptr, 512, 512);
    gemm_tc<1><<<dim3(1, BATCH / MT), blk, 2 * STAGE_BYTES>>>(
        h2H, h2L, wH + 196608, wL + 196608, b3, a3, nullptr, nullptr, out, 512, 256);
}

// round 11
// speedup vs baseline: 2.2137x; 1.0247x over previous
#include <cuda_runtime.h>
#include <cuda_fp16.h>
#include <cstdint>

// ---------------------------------------------------------------------------
// Network_1760936591970 (sm_103): fp16 2-split (Dekker) x 3-MMA emulated-fp32
// GEMM on mma.sync.m16n8k16.f16. 512-thread CTAs (16 warps, 64x32 warp tiles).
// R11: MMA dep-distance reorder (ni-pairs, distance 8) + single-barrier stage
// pipeline. Fast-tanh epilogue, fused row softmax in layer 3.
// 256 -> 512 -> 512 -> 256 MLP, B=65536, fp32 I/O.
// ---------------------------------------------------------------------------

#define BATCH 65536
#define MT 128
#define NT 256
#define BKT 64              // K elements per stage (fp16) = 128 B/row
#define STAGE_BYTES 98304   // Ah 16K | Al 16K | Bh 32K | Bl 32K
#define NTHREADS 512

// pre-split scratch (uint32 = packed half2 covering k,k+1)
__device__ uint32_t g_dH[BATCH * 128];     // data   [B][256/2]
__device__ uint32_t g_dL[BATCH * 128];
__device__ uint32_t g_h1H[BATCH * 256];    // h1     [B][512/2]
__device__ uint32_t g_h1L[BATCH * 256];
__device__ uint32_t g_h2H[BATCH * 256];    // h2     [B][512/2]
__device__ uint32_t g_h2L[BATCH * 256];
// weights transposed [N][K/2]: L1 @0, L2 @65536, L3 @196608
__device__ uint32_t g_wH[262144];
__device__ uint32_t g_wL[262144];

// ---------------- helpers ----------------
__device__ __forceinline__ void split_h(float x, uint16_t& h, uint16_t& l) {
    __half hh = __float2half_rn(x);
    __half ll = __float2half_rn(x - __half2float(hh));
    h = __half_as_ushort(hh);
    l = __half_as_ushort(ll);
}
__device__ __forceinline__ uint32_t pack2(uint16_t a, uint16_t b) {
    return (uint32_t)a | ((uint32_t)b << 16);
}
__device__ __forceinline__ uint32_t smem_u32(const void* p) {
    uint32_t a;
    asm("{ .reg .u64 t; cvta.to.shared.u64 t, %1; cvt.u32.u64 %0, t; }" : "=r"(a) : "l"(p));
    return a;
}
__device__ __forceinline__ void mma16(float* c, const uint32_t* a, uint32_t b0, uint32_t b1) {
    asm volatile(
        "mma.sync.aligned.m16n8k16.row.col.f32.f16.f16.f32 "
        "{%0,%1,%2,%3},{%4,%5,%6,%7},{%8,%9},{%0,%1,%2,%3};"
        : "+f"(c[0]), "+f"(c[1]), "+f"(c[2]), "+f"(c[3])
        : "r"(a[0]), "r"(a[1]), "r"(a[2]), "r"(a[3]), "r"(b0), "r"(b1));
}
__device__ __forceinline__ void cpa16(uint32_t dst, const void* src) {
    asm volatile("cp.async.cg.shared.global [%0], [%1], 16;" :: "r"(dst), "l"(src));
}
__device__ __forceinline__ float fast_tanh(float x) {
    float xc = fminf(fmaxf(x, -10.f), 10.f);
    float t = __expf(2.f * xc);
    return __fdividef(t - 1.f, t + 1.f);
}
__device__ __forceinline__ float act_f(float x, const float* a) {
    return a[1] * fast_tanh(x) * sinf(a[2] * x + a[3]) + a[4] * x + a[5];
}
#define ROWOFF(row, kbyte) ((row) * 128 + ((kbyte) ^ (((row) & 7) << 4)))

// ---------------- prep kernels ----------------
__global__ void prep_w(const float* __restrict__ W, uint32_t* __restrict__ th,
                       uint32_t* __restrict__ tl, int K, int N)
{
    int i = blockIdx.x * 256 + threadIdx.x;        // i = n*(K/2) + p
    const int Kp = K >> 1;
    if (i >= N * Kp) return;
    int n = i / Kp, p = i - n * Kp;
    uint16_t h0, l0, h1, l1;
    split_h(W[(size_t)(2 * p) * N + n], h0, l0);
    split_h(W[(size_t)(2 * p + 1) * N + n], h1, l1);
    th[i] = pack2(h0, h1);
    tl[i] = pack2(l0, l1);
}
__global__ void prep_a(const float* __restrict__ A, uint32_t* __restrict__ th,
                       uint32_t* __restrict__ tl, int n4)
{
    int i = blockIdx.x * 256 + threadIdx.x;
    if (i >= n4) return;
    float4 v = *(const float4*)(A + (size_t)i * 4);
    uint16_t h0, l0, h1, l1, h2, l2, h3, l3;
    split_h(v.x, h0, l0); split_h(v.y, h1, l1);
    split_h(v.z, h2, l2); split_h(v.w, h3, l3);
    th[2 * i]     = pack2(h0, h1);  tl[2 * i]     = pack2(l0, l1);
    th[2 * i + 1] = pack2(h2, h3);  tl[2 * i + 1] = pack2(l2, l3);
}

// ---------------- fused GEMM ----------------
// 16 warps: wm = warp&1 (64-row halves), wn = warp>>1 (8 x 32-col blocks).
// MODE 0: out = split(act(A@Wt + b)) packed -> outH/outL [M][Nn/2]
// MODE 1: out = softmax(act(A@Wt + b)) -> outF (Nn==256, grid.x==1)
template <int MODE>
__global__ void __launch_bounds__(NTHREADS, 1)
gemm_tc(const uint32_t* __restrict__ AH, const uint32_t* __restrict__ AL,
        const uint32_t* __restrict__ BH, const uint32_t* __restrict__ BL,
        const float* __restrict__ bias, const float* __restrict__ actp,
        uint32_t* __restrict__ outH, uint32_t* __restrict__ outL,
        float* __restrict__ outF, int K, int Nn)
{
    extern __shared__ char smem[];
    __shared__ float psm[NT * 6];

    const int tid  = threadIdx.x;
    const int lane = tid & 31;
    const int warp = tid >> 5;
    const int wm   = warp & 1;    // 0..1 -> 64-row half
    const int wn   = warp >> 1;   // 0..7 -> 32-col block
    const int g    = lane >> 2;
    const int tg   = lane & 3;
    const int m0   = blockIdx.y * MT;
    const int n0   = blockIdx.x * NT;
    const int Kp   = K >> 1;
    const uint32_t sb = smem_u32(smem);

    for (int c = tid; c < NT; c += NTHREADS) {
        psm[c * 6 + 0] = bias[n0 + c];
        #pragma unroll
        for (int j = 0; j < 5; j++) psm[c * 6 + 1 + j] = actp[(n0 + c) * 5 + j];
    }

    float acc[4][4][4];
    #pragma unroll
    for (int i = 0; i < 4; i++)
        #pragma unroll
        for (int j = 0; j < 4; j++)
            #pragma unroll
            for (int c = 0; c < 4; c++) acc[i][j][c] = 0.f;

    const int kIters = K / BKT;
    const int am = tid >> 3, aq = tid & 7;    // A rows 0..63 (+64), chunk 0..7
    const int bn = tid >> 3, bq = tid & 7;    // B rows 0..63 (+64,128,192)

    auto issue = [&](int it) {
        const uint32_t stb = sb + (it & 1) * STAGE_BYTES;
        const int p0 = it * 32;
        #pragma unroll
        for (int i = 0; i < 2; i++) {          // A hi+lo: 128 rows
            const int m = am + i * 64;
            const uint32_t off = ROWOFF(m, aq * 16);
            const size_t src = (size_t)(m0 + m) * Kp + p0 + aq * 4;
            cpa16(stb + off,         AH + src);
            cpa16(stb + 16384 + off, AL + src);
        }
        #pragma unroll
        for (int i = 0; i < 4; i++) {          // B hi+lo: 256 rows
            const int n = bn + i * 64;
            const uint32_t off = ROWOFF(n, bq * 16);
            const size_t src = (size_t)(n0 + n) * Kp + p0 + bq * 4;
            cpa16(stb + 32768 + off, BH + src);
            cpa16(stb + 65536 + off, BL + src);
        }
        asm volatile("cp.async.commit_group;" ::: "memory");
    };

    issue(0);

    for (int it = 0; it < kIters; it++) {
        // drain the group that filled stage (it & 1)
        asm volatile("cp.async.wait_group 0;" ::: "memory");
        __syncthreads();
        // overwrite of stage (it+1)&1 is safe: all warps passed iter it-1's
        // reads of that stage before this barrier.
        if (it + 1 < kIters) issue(it + 1);

        const char* st = smem + (it & 1) * STAGE_BYTES;
        #pragma unroll
        for (int kk = 0; kk < 4; kk++) {       // 4 k16-slices per stage
            const int pA = kk * 8 + tg;
            uint32_t ah[4][4], al[4][4];
            #pragma unroll
            for (int mi = 0; mi < 4; mi++) {
                const int m = wm * 64 + mi * 16 + g;
                const uint32_t o00 = ROWOFF(m,     pA * 4);
                const uint32_t o10 = ROWOFF(m + 8, pA * 4);
                const uint32_t o01 = ROWOFF(m,     (pA + 4) * 4);
                const uint32_t o11 = ROWOFF(m + 8, (pA + 4) * 4);
                ah[mi][0] = *(const uint32_t*)(st + o00);
                ah[mi][1] = *(const uint32_t*)(st + o10);
                ah[mi][2] = *(const uint32_t*)(st + o01);
                ah[mi][3] = *(const uint32_t*)(st + o11);
                al[mi][0] = *(const uint32_t*)(st + 16384 + o00);
                al[mi][1] = *(const uint32_t*)(st + 16384 + o10);
                al[mi][2] = *(const uint32_t*)(st + 16384 + o01);
                al[mi][3] = *(const uint32_t*)(st + 16384 + o11);
            }
            // ni-pairs: dep distance 8 between writes to the same accumulator
            #pragma unroll
            for (int np = 0; np < 2; np++) {
                uint32_t bh[2][2], bl[2][2];
                #pragma unroll
                for (int p = 0; p < 2; p++) {
                    const int n = wn * 32 + (np * 2 + p) * 8 + g;
                    const uint32_t o0 = ROWOFF(n, pA * 4);
                    const uint32_t o1 = ROWOFF(n, (pA + 4) * 4);
                    bh[p][0] = *(const uint32_t*)(st + 32768 + o0);
                    bh[p][1] = *(const uint32_t*)(st + 32768 + o1);
                    bl[p][0] = *(const uint32_t*)(st + 65536 + o0);
                    bl[p][1] = *(const uint32_t*)(st + 65536 + o1);
                }
                #pragma unroll
                for (int p = 0; p < 2; p++)
                    #pragma unroll
                    for (int mi = 0; mi < 4; mi++)
                        mma16(acc[mi][np * 2 + p], ah[mi], bh[p][0], bh[p][1]);
                #pragma unroll
                for (int p = 0; p < 2; p++)
                    #pragma unroll
                    for (int mi = 0; mi < 4; mi++)
                        mma16(acc[mi][np * 2 + p], al[mi], bh[p][0], bh[p][1]);
                #pragma unroll
                for (int p = 0; p < 2; p++)
                    #pragma unroll
                    for (int mi = 0; mi < 4; mi++)
                        mma16(acc[mi][np * 2 + p], ah[mi], bl[p][0], bl[p][1]);
            }
        }
    }

    // ---- epilogue: bias + activation ----
    #pragma unroll
    for (int mi = 0; mi < 4; mi++)
        #pragma unroll
        for (int ni = 0; ni < 4; ni++) {
            const int cw = wn * 32 + ni * 8 + 2 * tg;
            const float* p0 = &psm[cw * 6];
            const float* p1 = &psm[(cw + 1) * 6];
            acc[mi][ni][0] = act_f(acc[mi][ni][0] + p0[0], p0);
            acc[mi][ni][1] = act_f(acc[mi][ni][1] + p1[0], p1);
            acc[mi][ni][2] = act_f(acc[mi][ni][2] + p0[0], p0);
            acc[mi][ni][3] = act_f(acc[mi][ni][3] + p1[0], p1);
        }

    if (MODE == 0) {
        const int Np = Nn >> 1;
        #pragma unroll
        for (int mi = 0; mi < 4; mi++)
            #pragma unroll
            for (int ni = 0; ni < 4; ni++) {
                const int cw = wn * 32 + ni * 8 + 2 * tg;
                const int cp = (n0 + cw) >> 1;
                const int r0 = m0 + wm * 64 + mi * 16 + g;
                uint16_t h0, l0, h1, l1;
                split_h(acc[mi][ni][0], h0, l0);
                split_h(acc[mi][ni][1], h1, l1);
                outH[(size_t)r0 * Np + cp] = pack2(h0, h1);
                outL[(size_t)r0 * Np + cp] = pack2(l0, l1);
                split_h(acc[mi][ni][2], h0, l0);
                split_h(acc[mi][ni][3], h1, l1);
                outH[(size_t)(r0 + 8) * Np + cp] = pack2(h0, h1);
                outL[(size_t)(r0 + 8) * Np + cp] = pack2(l0, l1);
            }
    } else {
        // fused softmax over full row (Nn == 256 in this CTA); 8 wn partials
        float* red = (float*)smem;   // [128 rows][8]
        float pmax[4][2], rmax[4][2], psum[4][2], rsum[4][2];

        #pragma unroll
        for (int mi = 0; mi < 4; mi++)
            #pragma unroll
            for (int h = 0; h < 2; h++) {
                float v = -3.4e38f;
                #pragma unroll
                for (int ni = 0; ni < 4; ni++)
                    v = fmaxf(v, fmaxf(acc[mi][ni][2 * h], acc[mi][ni][2 * h + 1]));
                v = fmaxf(v, __shfl_xor_sync(0xFFFFFFFFu, v, 1));
                v = fmaxf(v, __shfl_xor_sync(0xFFFFFFFFu, v, 2));
                pmax[mi][h] = v;
            }
        __syncthreads();   // mainloop smem reads done before reuse as 'red'
        if (tg == 0)
            #pragma unroll
            for (int mi = 0; mi < 4; mi++)
                #pragma unroll
                for (int h = 0; h < 2; h++)
                    red[(wm * 64 + mi * 16 + g + 8 * h) * 8 + wn] = pmax[mi][h];
        __syncthreads();
        #pragma unroll
        for (int mi = 0; mi < 4; mi++)
            #pragma unroll
            for (int h = 0; h < 2; h++) {
                const int wr = wm * 64 + mi * 16 + g + 8 * h;
                float v = red[wr * 8 + 0];
                #pragma unroll
                for (int j = 1; j < 8; j++) v = fmaxf(v, red[wr * 8 + j]);
                rmax[mi][h] = v;
            }
        __syncthreads();

        #pragma unroll
        for (int mi = 0; mi < 4; mi++)
            #pragma unroll
            for (int h = 0; h < 2; h++) {
                float s = 0.f;
                #pragma unroll
                for (int ni = 0; ni < 4; ni++) {
                    float e0 = __expf(acc[mi][ni][2 * h]     - rmax[mi][h]);
                    float e1 = __expf(acc[mi][ni][2 * h + 1] - rmax[mi][h]);
                    acc[mi][ni][2 * h]     = e0;
                    acc[mi][ni][2 * h + 1] = e1;
                    s += e0 + e1;
                }
                s += __shfl_xor_sync(0xFFFFFFFFu, s, 1);
                s += __shfl_xor_sync(0xFFFFFFFFu, s, 2);
                psum[mi][h] = s;
            }
        if (tg == 0)
            #pragma unroll
            for (int mi = 0; mi < 4; mi++)
                #pragma unroll
                for (int h = 0; h < 2; h++)
                    red[(wm * 64 + mi * 16 + g + 8 * h) * 8 + wn] = psum[mi][h];
        __syncthreads();
        #pragma unroll
        for (int mi = 0; mi < 4; mi++)
            #pragma unroll
            for (int h = 0; h < 2; h++) {
                const int wr = wm * 64 + mi * 16 + g + 8 * h;
                float s = red[wr * 8 + 0];
                #pragma unroll
                for (int j = 1; j < 8; j++) s += red[wr * 8 + j];
                rsum[mi][h] = 1.0f / s;
            }

        #pragma unroll
        for (int mi = 0; mi < 4; mi++)
            #pragma unroll
            for (int ni = 0; ni < 4; ni++) {
                const int col = wn * 32 + ni * 8 + 2 * tg;
                const int r0 = m0 + wm * 64 + mi * 16 + g;
                *(float2*)(outF + (size_t)r0 * 256 + col) =
                    make_float2(acc[mi][ni][0] * rsum[mi][0],
                                acc[mi][ni][1] * rsum[mi][0]);
                *(float2*)(outF + (size_t)(r0 + 8) * 256 + col) =
                    make_float2(acc[mi][ni][2] * rsum[mi][1],
                                acc[mi][ni][3] * rsum[mi][1]);
            }
    }
}

// ---------------- launch ----------------
extern "C" void kernel_launch(void* const* d_in, const int* in_sizes, int n_in,
                              void* d_out, int out_size)
{
    (void)in_sizes; (void)n_in; (void)out_size;
    const float* data = (const float*)d_in[0];
    const float* W1   = (const float*)d_in[1];
    const float* b1   = (const float*)d_in[2];
    const float* a1   = (const float*)d_in[3];
    const float* W2   = (const float*)d_in[4];
    const float* b2   = (const float*)d_in[5];
    const float* a2   = (const float*)d_in[6];
    const float* W3   = (const float*)d_in[7];
    const float* b3   = (const float*)d_in[8];
    const float* a3   = (const float*)d_in[9];
    float* out = (float*)d_out;

    void* p;
    cudaGetSymbolAddress(&p, g_dH);  uint32_t* dH  = (uint32_t*)p;
    cudaGetSymbolAddress(&p, g_dL);  uint32_t* dL  = (uint32_t*)p;
    cudaGetSymbolAddress(&p, g_h1H); uint32_t* h1H = (uint32_t*)p;
    cudaGetSymbolAddress(&p, g_h1L); uint32_t* h1L = (uint32_t*)p;
    cudaGetSymbolAddress(&p, g_h2H); uint32_t* h2H = (uint32_t*)p;
    cudaGetSymbolAddress(&p, g_h2L); uint32_t* h2L = (uint32_t*)p;
    cudaGetSymbolAddress(&p, g_wH);  uint32_t* wH  = (uint32_t*)p;
    cudaGetSymbolAddress(&p, g_wL);  uint32_t* wL  = (uint32_t*)p;

    cudaFuncSetAttribute(gemm_tc<0>, cudaFuncAttributeMaxDynamicSharedMemorySize,
                         2 * STAGE_BYTES);
    cudaFuncSetAttribute(gemm_tc<1>, cudaFuncAttributeMaxDynamicSharedMemorySize,
                         2 * STAGE_BYTES);

    prep_w<<<(65536  + 255) / 256, 256>>>(W1, wH,          wL,          256, 512);
    prep_w<<<(131072 + 255) / 256, 256>>>(W2, wH + 65536,  wL + 65536,  512, 512);
    prep_w<<<(65536  + 255) / 256, 256>>>(W3, wH + 196608, wL + 196608, 512, 256);
    prep_a<<<(BATCH * 64 + 255) / 256, 256>>>(data, dH, dL, BATCH * 64);

    dim3 blk(NTHREADS);
    gemm_tc<0><<<dim3(2, BATCH / MT), blk, 2 * STAGE_BYTES>>>(
        dH, dL, wH, wL, b1, a1, h1H, h1L, nullptr, 256, 512);
    gemm_tc<0><<<dim3(2, BATCH / MT), blk, 2 * STAGE_BYTES>>>(
        h1H, h1L, wH + 65536, wL + 65536, b2, a2, h2H, h2L, nullptr, 512, 512);
    gemm_tc<1><<<dim3(1, BATCH / MT), blk, 2 * STAGE_BYTES>>>(
        h2H, h2L, wH + 196608, wL + 196608, b3, a3, nullptr, nullptr, out, 512, 256);
}